// round 7
// baseline (speedup 1.0000x reference)
#include <cuda_runtime.h>
#include <math.h>
#include <stdint.h>

// Problem constants
#define D_MODEL 1024
#define NHEAD   16
#define DKH     64
#define NLAYER  8
#define FF_DIM  4096
#define BATCH   4
#define TGT     512
#define SRCL    256
#define VOCAB   32000
#define ROWS_X  (BATCH*TGT)   // 2048
#define ROWS_E  (BATCH*SRCL)  // 1024

// ---------------- scratch (device globals; no allocation allowed) ----------
__device__ float g_x   [ROWS_X*(size_t)D_MODEL];
__device__ float g_enc [ROWS_E*(size_t)D_MODEL];
__device__ float g_q   [ROWS_X*(size_t)D_MODEL];
__device__ float g_k   [ROWS_X*(size_t)D_MODEL];
__device__ float g_v   [ROWS_X*(size_t)D_MODEL];
__device__ float g_attn[ROWS_X*(size_t)D_MODEL];
__device__ float g_tmp [ROWS_X*(size_t)D_MODEL];
__device__ float g_ff  [ROWS_X*(size_t)FF_DIM];

// ---------------- positional encoding -------------------------------------
__device__ __forceinline__ float pe_val(int pos, int c) {
    int i2 = c & ~1;  // even index 2i
    float div = expf((float)i2 * (-9.210340371976184f / (float)D_MODEL)); // ln(10000)
    float ang = (float)pos * div;
    return (c & 1) ? cosf(ang) : sinf(ang);
}

// x[b,t,:] = emb[tgt[b,t],:] + pe(t,:)
__global__ void embed_kernel(const int* __restrict__ tgt,
                             const float* __restrict__ emb,
                             float* __restrict__ x) {
    int row = blockIdx.x;           // b*TGT + t
    int t = row % TGT;
    int token = tgt[row];
    const float* erow = emb + (size_t)token * D_MODEL;
    float* xrow = x + (size_t)row * D_MODEL;
    for (int c = threadIdx.x; c < D_MODEL; c += blockDim.x)
        xrow[c] = erow[c] + pe_val(t, c);
}

// enc[b,s,:] = src[b,s,:] + pe(s,:)
__global__ void encpe_kernel(const float* __restrict__ src,
                             float* __restrict__ enc) {
    int row = blockIdx.x;           // b*SRCL + s
    int s = row % SRCL;
    const float* srow = src + (size_t)row * D_MODEL;
    float* erow = enc + (size_t)row * D_MODEL;
    for (int c = threadIdx.x; c < D_MODEL; c += blockDim.x)
        erow[c] = srow[c] + pe_val(s, c);
}

// ---------------- SGEMM: C[M,N] = A[M,K] @ B[K,N] + bias (opt ReLU) --------
// 128x128 block tile, BK=8, 256 threads, 8x8 per-thread, register prefetch.
// Requires M%128==0, N%128==0, K%8==0 (holds for every GEMM in this model).
template<bool RELU>
__global__ __launch_bounds__(256, 2)
void sgemm_bias(const float* __restrict__ A, const float* __restrict__ B,
                const float* __restrict__ bias, float* __restrict__ C,
                int M, int N, int K) {
    __shared__ float As[8][128];
    __shared__ float Bs[8][128];
    const int bx = blockIdx.x;      // N tile
    const int by = blockIdx.y;      // M tile
    const int tid = threadIdx.x;

    const int arow = tid >> 1;            // 0..127
    const int acol = (tid & 1) * 4;       // 0 or 4
    const int brow = tid >> 5;            // 0..7
    const int bcol = (tid & 31) * 4;      // 0..124

    const float* Aptr = A + (size_t)(by * 128 + arow) * K + acol;
    const float* Bptr = B + (size_t)brow * N + (size_t)bx * 128 + bcol;

    const int tr = (tid >> 4) << 3;       // output row base within tile
    const int tc = (tid & 15) << 3;       // output col base within tile

    float acc[8][8];
    #pragma unroll
    for (int i = 0; i < 8; i++)
        #pragma unroll
        for (int j = 0; j < 8; j++) acc[i][j] = 0.f;

    float4 a4 = *(const float4*)Aptr;
    float4 b4 = *(const float4*)Bptr;

    for (int k0 = 0; k0 < K; k0 += 8) {
        As[acol + 0][arow] = a4.x;
        As[acol + 1][arow] = a4.y;
        As[acol + 2][arow] = a4.z;
        As[acol + 3][arow] = a4.w;
        *(float4*)&Bs[brow][bcol] = b4;
        __syncthreads();

        if (k0 + 8 < K) {
            Aptr += 8;
            Bptr += (size_t)8 * N;
            a4 = *(const float4*)Aptr;
            b4 = *(const float4*)Bptr;
        }

        #pragma unroll
        for (int kk = 0; kk < 8; kk++) {
            float ra[8], rb[8];
            #pragma unroll
            for (int i = 0; i < 8; i++) ra[i] = As[kk][tr + i];
            #pragma unroll
            for (int j = 0; j < 8; j++) rb[j] = Bs[kk][tc + j];
            #pragma unroll
            for (int i = 0; i < 8; i++)
                #pragma unroll
                for (int j = 0; j < 8; j++)
                    acc[i][j] += ra[i] * rb[j];
        }
        __syncthreads();
    }

    // epilogue: bias (+ReLU), vectorized stores
    #pragma unroll
    for (int i = 0; i < 8; i++) {
        float* crow = C + (size_t)(by * 128 + tr + i) * N + (size_t)bx * 128 + tc;
        #pragma unroll
        for (int j = 0; j < 8; j += 4) {
            float4 o;
            o.x = acc[i][j + 0] + bias[bx * 128 + tc + j + 0];
            o.y = acc[i][j + 1] + bias[bx * 128 + tc + j + 1];
            o.z = acc[i][j + 2] + bias[bx * 128 + tc + j + 2];
            o.w = acc[i][j + 3] + bias[bx * 128 + tc + j + 3];
            if (RELU) {
                o.x = fmaxf(o.x, 0.f); o.y = fmaxf(o.y, 0.f);
                o.z = fmaxf(o.z, 0.f); o.w = fmaxf(o.w, 0.f);
            }
            *(float4*)&crow[j] = o;
        }
    }
}

// ---------------- attention ------------------------------------------------
// grid: (TGT/8, NHEAD, BATCH), 256 threads. Block handles 8 query rows of one
// (b,h). Scores kept in smem; K/V streamed as 64-row tiles.
// MASKED: self-attn mask = (tgt[b,q]!=0) && (k<=q), else -1e9.
template<bool MASKED>
__global__ __launch_bounds__(256)
void attn_kernel(const float* __restrict__ q, const float* __restrict__ k,
                 const float* __restrict__ v, const int* __restrict__ tgt,
                 float* __restrict__ out, int Skv) {
    const int qt = blockIdx.x, h = blockIdx.y, b = blockIdx.z;
    const int qbase = qt * 8;
    const int tid = threadIdx.x;

    __shared__ float qs[8][DKH];
    __shared__ float ks[64][65];      // padded: conflict-free both axes
    __shared__ float sc[8][TGT];      // scores/probs (max Skv = 512)
    __shared__ int   rowok[8];

    // load q tile (+ row masks)
    for (int i = tid; i < 8 * DKH; i += 256) {
        int qi = i >> 6, d = i & 63;
        qs[qi][d] = q[((size_t)(b * TGT + qbase + qi)) * D_MODEL + h * DKH + d];
    }
    if (MASKED && tid < 8)
        rowok[tid] = (tgt[b * TGT + qbase + tid] != 0);
    __syncthreads();

    const int qi0 = tid >> 6;   // 0..3 (also handles qi0+4)
    const int kj  = tid & 63;

    // scores
    for (int kt = 0; kt < Skv; kt += 64) {
        for (int i = tid; i < 64 * 16; i += 256) {       // 1024 float4 loads
            int r = i >> 4, c4 = (i & 15) * 4;
            float4 f = *(const float4*)&k[((size_t)(b * Skv + kt + r)) * D_MODEL + h * DKH + c4];
            ks[r][c4 + 0] = f.x; ks[r][c4 + 1] = f.y;
            ks[r][c4 + 2] = f.z; ks[r][c4 + 3] = f.w;
        }
        __syncthreads();
        #pragma unroll
        for (int half = 0; half < 2; half++) {
            int qi = qi0 + half * 4;
            float acc = 0.f;
            #pragma unroll
            for (int d = 0; d < DKH; d++) acc += qs[qi][d] * ks[kj][d];
            float s = acc * 0.125f;      // 1/sqrt(64)
            int kglob = kt + kj;
            if (MASKED) {
                bool ok = (kglob <= qbase + qi) && rowok[qi];
                if (!ok) s = -1e9f;
            }
            sc[qi][kglob] = s;
        }
        __syncthreads();
    }

    // softmax: one warp per query row (8 warps)
    {
        int w = tid >> 5, lane = tid & 31;
        float m = -INFINITY;
        for (int j = lane; j < Skv; j += 32) m = fmaxf(m, sc[w][j]);
        #pragma unroll
        for (int o = 16; o; o >>= 1) m = fmaxf(m, __shfl_xor_sync(~0u, m, o));
        float ssum = 0.f;
        for (int j = lane; j < Skv; j += 32) {
            float e = __expf(sc[w][j] - m);
            sc[w][j] = e;
            ssum += e;
        }
        #pragma unroll
        for (int o = 16; o; o >>= 1) ssum += __shfl_xor_sync(~0u, ssum, o);
        float inv = 1.f / ssum;
        for (int j = lane; j < Skv; j += 32) sc[w][j] *= inv;
    }
    __syncthreads();

    // out = probs @ V  (reuse ks as V tile)
    const int d = tid & 63;
    float o0 = 0.f, o1 = 0.f;
    for (int kt = 0; kt < Skv; kt += 64) {
        for (int i = tid; i < 64 * 16; i += 256) {
            int r = i >> 4, c4 = (i & 15) * 4;
            float4 f = *(const float4*)&v[((size_t)(b * Skv + kt + r)) * D_MODEL + h * DKH + c4];
            ks[r][c4 + 0] = f.x; ks[r][c4 + 1] = f.y;
            ks[r][c4 + 2] = f.z; ks[r][c4 + 3] = f.w;
        }
        __syncthreads();
        #pragma unroll 16
        for (int kk = 0; kk < 64; kk++) {
            float vv = ks[kk][d];
            o0 += sc[qi0    ][kt + kk] * vv;
            o1 += sc[qi0 + 4][kt + kk] * vv;
        }
        __syncthreads();
    }
    out[((size_t)(b * TGT + qbase + qi0    )) * D_MODEL + h * DKH + d] = o0;
    out[((size_t)(b * TGT + qbase + qi0 + 4)) * D_MODEL + h * DKH + d] = o1;
}

// ---------------- add + LayerNorm (in place on x) --------------------------
// grid: ROWS_X blocks, 256 threads; row length D_MODEL=1024 (4 per thread)
__global__ __launch_bounds__(256)
void add_ln_kernel(float* __restrict__ x, const float* __restrict__ a,
                   const float* __restrict__ g, const float* __restrict__ bb) {
    __shared__ float scratch[8];
    __shared__ float mu_s, rstd_s;
    const int row = blockIdx.x, tid = threadIdx.x;
    float* xrow = x + (size_t)row * D_MODEL;
    const float* arow = a + (size_t)row * D_MODEL;

    float vals[4];
    float s = 0.f;
    #pragma unroll
    for (int i = 0; i < 4; i++) {
        int c = tid + i * 256;
        vals[i] = xrow[c] + arow[c];
        s += vals[i];
    }
    // reduce sum
    #pragma unroll
    for (int o = 16; o; o >>= 1) s += __shfl_xor_sync(~0u, s, o);
    if ((tid & 31) == 0) scratch[tid >> 5] = s;
    __syncthreads();
    if (tid == 0) {
        float t = 0.f;
        #pragma unroll
        for (int w = 0; w < 8; w++) t += scratch[w];
        mu_s = t * (1.f / D_MODEL);
    }
    __syncthreads();
    const float mu = mu_s;

    float vsum = 0.f;
    #pragma unroll
    for (int i = 0; i < 4; i++) {
        float d = vals[i] - mu;
        vsum += d * d;
    }
    #pragma unroll
    for (int o = 16; o; o >>= 1) vsum += __shfl_xor_sync(~0u, vsum, o);
    if ((tid & 31) == 0) scratch[tid >> 5] = vsum;
    __syncthreads();
    if (tid == 0) {
        float t = 0.f;
        #pragma unroll
        for (int w = 0; w < 8; w++) t += scratch[w];
        rstd_s = rsqrtf(t * (1.f / D_MODEL) + 1e-5f);
    }
    __syncthreads();
    const float r = rstd_s;

    #pragma unroll
    for (int i = 0; i < 4; i++) {
        int c = tid + i * 256;
        xrow[c] = (vals[i] - mu) * r * g[c] + bb[c];
    }
}

// ---------------- host orchestration ---------------------------------------
static inline dim3 gemm_grid(int M, int N) { return dim3(N / 128, M / 128); }

extern "C" void kernel_launch(void* const* d_in, const int* in_sizes, int n_in,
                              void* d_out, int out_size) {
    // ---- input binding -----------------------------------------------------
    // The harness passes inputs in metadata.txt order = setup_inputs() dict
    // insertion order:
    //   0 src, 1 tgt, 2 emb, 3 fc_w, 4 fc_b,
    //   5 sa_wq, 6 sa_bq, 7 sa_wk, 8 sa_bk, 9 sa_wv, 10 sa_bv, 11 sa_wo, 12 sa_bo,
    //   13 ca_wq, 14 ca_bq, 15 ca_wk, 16 ca_bk, 17 ca_wv, 18 ca_bv, 19 ca_wo, 20 ca_bo,
    //   21 w1, 22 b1, 23 w2, 24 b2,
    //   25 n1g, 26 n2g, 27 n3g, 28 n1b, 29 n2b, 30 n3b
    // Runtime disambiguation vs. reference-signature order: in_sizes[3] is
    // fc_w (D*V = 32,768,000) under dict order but sa_wq (L*D*D = 8,388,608)
    // under signature order.
    const float *src, *emb, *fc_w, *fc_b;
    const int* tgt;
    const float *sa_wq, *sa_bq, *sa_wk, *sa_bk, *sa_wv, *sa_bv, *sa_wo, *sa_bo;
    const float *ca_wq, *ca_bq, *ca_wk, *ca_bk, *ca_wv, *ca_bv, *ca_wo, *ca_bo;
    const float *w1, *b1, *w2, *b2;
    const float *n1g, *n1b, *n2g, *n2b, *n3g, *n3b;

    src = (const float*)d_in[0];
    tgt = (const int*)  d_in[1];
    emb = (const float*)d_in[2];

    if (in_sizes[3] == (int)((size_t)D_MODEL * VOCAB)) {
        // ---- dict insertion order (expected) ----
        fc_w  = (const float*)d_in[3];
        fc_b  = (const float*)d_in[4];
        sa_wq = (const float*)d_in[5];   sa_bq = (const float*)d_in[6];
        sa_wk = (const float*)d_in[7];   sa_bk = (const float*)d_in[8];
        sa_wv = (const float*)d_in[9];   sa_bv = (const float*)d_in[10];
        sa_wo = (const float*)d_in[11];  sa_bo = (const float*)d_in[12];
        ca_wq = (const float*)d_in[13];  ca_bq = (const float*)d_in[14];
        ca_wk = (const float*)d_in[15];  ca_bk = (const float*)d_in[16];
        ca_wv = (const float*)d_in[17];  ca_bv = (const float*)d_in[18];
        ca_wo = (const float*)d_in[19];  ca_bo = (const float*)d_in[20];
        w1    = (const float*)d_in[21];  b1    = (const float*)d_in[22];
        w2    = (const float*)d_in[23];  b2    = (const float*)d_in[24];
        n1g   = (const float*)d_in[25];
        n2g   = (const float*)d_in[26];
        n3g   = (const float*)d_in[27];
        n1b   = (const float*)d_in[28];
        n2b   = (const float*)d_in[29];
        n3b   = (const float*)d_in[30];
    } else {
        // ---- reference signature order (fallback) ----
        sa_wq = (const float*)d_in[3];   sa_bq = (const float*)d_in[4];
        sa_wk = (const float*)d_in[5];   sa_bk = (const float*)d_in[6];
        sa_wv = (const float*)d_in[7];   sa_bv = (const float*)d_in[8];
        sa_wo = (const float*)d_in[9];   sa_bo = (const float*)d_in[10];
        ca_wq = (const float*)d_in[11];  ca_bq = (const float*)d_in[12];
        ca_wk = (const float*)d_in[13];  ca_bk = (const float*)d_in[14];
        ca_wv = (const float*)d_in[15];  ca_bv = (const float*)d_in[16];
        ca_wo = (const float*)d_in[17];  ca_bo = (const float*)d_in[18];
        w1    = (const float*)d_in[19];  b1    = (const float*)d_in[20];
        w2    = (const float*)d_in[21];  b2    = (const float*)d_in[22];
        n1g   = (const float*)d_in[23];  n1b   = (const float*)d_in[24];
        n2g   = (const float*)d_in[25];  n2b   = (const float*)d_in[26];
        n3g   = (const float*)d_in[27];  n3b   = (const float*)d_in[28];
        fc_w  = (const float*)d_in[29];
        fc_b  = (const float*)d_in[30];
    }
    float* out = (float*)d_out;

    float *x, *enc, *q, *k, *v, *attn, *tmp, *ff;
    cudaGetSymbolAddress((void**)&x,    g_x);
    cudaGetSymbolAddress((void**)&enc,  g_enc);
    cudaGetSymbolAddress((void**)&q,    g_q);
    cudaGetSymbolAddress((void**)&k,    g_k);
    cudaGetSymbolAddress((void**)&v,    g_v);
    cudaGetSymbolAddress((void**)&attn, g_attn);
    cudaGetSymbolAddress((void**)&tmp,  g_tmp);
    cudaGetSymbolAddress((void**)&ff,   g_ff);

    embed_kernel<<<ROWS_X, 256>>>(tgt, emb, x);
    encpe_kernel<<<ROWS_E, 256>>>(src, enc);

    for (int l = 0; l < NLAYER; l++) {
        const size_t wo  = (size_t)l * D_MODEL * D_MODEL;
        const size_t bo  = (size_t)l * D_MODEL;
        const size_t w1o = (size_t)l * D_MODEL * FF_DIM;
        const size_t b1o = (size_t)l * FF_DIM;

        // ---- self attention ----
        sgemm_bias<false><<<gemm_grid(ROWS_X, D_MODEL), 256>>>(x, sa_wq + wo, sa_bq + bo, q, ROWS_X, D_MODEL, D_MODEL);
        sgemm_bias<false><<<gemm_grid(ROWS_X, D_MODEL), 256>>>(x, sa_wk + wo, sa_bk + bo, k, ROWS_X, D_MODEL, D_MODEL);
        sgemm_bias<false><<<gemm_grid(ROWS_X, D_MODEL), 256>>>(x, sa_wv + wo, sa_bv + bo, v, ROWS_X, D_MODEL, D_MODEL);
        attn_kernel<true><<<dim3(TGT / 8, NHEAD, BATCH), 256>>>(q, k, v, tgt, attn, TGT);
        sgemm_bias<false><<<gemm_grid(ROWS_X, D_MODEL), 256>>>(attn, sa_wo + wo, sa_bo + bo, tmp, ROWS_X, D_MODEL, D_MODEL);
        add_ln_kernel<<<ROWS_X, 256>>>(x, tmp, n1g + bo, n1b + bo);

        // ---- cross attention ----
        sgemm_bias<false><<<gemm_grid(ROWS_X, D_MODEL), 256>>>(x, ca_wq + wo, ca_bq + bo, q, ROWS_X, D_MODEL, D_MODEL);
        sgemm_bias<false><<<gemm_grid(ROWS_E, D_MODEL), 256>>>(enc, ca_wk + wo, ca_bk + bo, k, ROWS_E, D_MODEL, D_MODEL);
        sgemm_bias<false><<<gemm_grid(ROWS_E, D_MODEL), 256>>>(enc, ca_wv + wo, ca_bv + bo, v, ROWS_E, D_MODEL, D_MODEL);
        attn_kernel<false><<<dim3(TGT / 8, NHEAD, BATCH), 256>>>(q, k, v, nullptr, attn, SRCL);
        sgemm_bias<false><<<gemm_grid(ROWS_X, D_MODEL), 256>>>(attn, ca_wo + wo, ca_bo + bo, tmp, ROWS_X, D_MODEL, D_MODEL);
        add_ln_kernel<<<ROWS_X, 256>>>(x, tmp, n2g + bo, n2b + bo);

        // ---- feed forward ----
        sgemm_bias<true ><<<gemm_grid(ROWS_X, FF_DIM), 256>>>(x, w1 + w1o, b1 + b1o, ff, ROWS_X, FF_DIM, D_MODEL);
        sgemm_bias<false><<<gemm_grid(ROWS_X, D_MODEL), 256>>>(ff, w2 + w1o, b2 + bo, tmp, ROWS_X, D_MODEL, FF_DIM);
        add_ln_kernel<<<ROWS_X, 256>>>(x, tmp, n3g + bo, n3b + bo);
    }

    // ---- final projection to vocab ----
    sgemm_bias<false><<<gemm_grid(ROWS_X, VOCAB), 256>>>(x, fc_w, fc_b, out, ROWS_X, VOCAB, D_MODEL);
}